// round 15
// baseline (speedup 1.0000x reference)
#include <cuda_runtime.h>
#include <cuda_fp16.h>

#define BB    2
#define CC    64
#define NN    16384
#define KK    16
#define COUT  64
#define RR    128           // rows of combined matrix [W1-W2 ; W2]
#define TNB   64            // GEMM nodes per block

typedef unsigned long long ull;

// ---------------- scratch (device globals; no allocation allowed) ----------
__device__ float  g_mean[BB][CC];
__device__ float  g_cvec[BB][COUT];
__device__ float  g_Mt[CC][RR];                // transposed combined matrix [c][r]
__device__ __half g_Yh[(size_t)BB * NN * RR];  // 8 MB transformed features (fp16)
__device__ int    g_is64;

// ---------------- f32x2 helpers (sm_103a packed fp32 FMA) -------------------
#define FMA_F32X2(d, a, b) \
    asm("fma.rn.f32x2 %0, %1, %2, %0;" : "+l"(d) : "l"(a), "l"(b))

__device__ __forceinline__ ull pack2(float lo, float hi) {
    ull r;
    asm("mov.b64 %0, {%1, %2};" : "=l"(r) : "f"(lo), "f"(hi));
    return r;
}

// ---------------- mean over nodes: g_mean[b][c] -----------------------------
__global__ __launch_bounds__(256) void mean_kernel(const float* __restrict__ x) {
    int row = blockIdx.x;                 // b*CC + c
    const float4* xr = (const float4*)(x + (size_t)row * NN);
    int tid = threadIdx.x;

    float4 v[16];
    #pragma unroll
    for (int it = 0; it < 16; it++)
        v[it] = xr[tid + it * 256];

    float s0 = 0.f, s1 = 0.f, s2 = 0.f, s3 = 0.f;
    #pragma unroll
    for (int it = 0; it < 16; it += 4) {
        s0 += v[it    ].x + v[it    ].y + v[it    ].z + v[it    ].w;
        s1 += v[it + 1].x + v[it + 1].y + v[it + 1].z + v[it + 1].w;
        s2 += v[it + 2].x + v[it + 2].y + v[it + 2].z + v[it + 2].w;
        s3 += v[it + 3].x + v[it + 3].y + v[it + 3].z + v[it + 3].w;
    }
    float s = (s0 + s1) + (s2 + s3);

    #pragma unroll
    for (int off = 16; off > 0; off >>= 1)
        s += __shfl_xor_sync(0xFFFFFFFFu, s, off);

    __shared__ float sm[8];
    if ((tid & 31) == 0) sm[tid >> 5] = s;
    __syncthreads();
    if (tid == 0) {
        float t = 0.f;
        #pragma unroll
        for (int w = 0; w < 8; w++) t += sm[w];
        ((float*)g_mean)[row] = t * (1.0f / NN);
    }
}

// ---------------- build Mt, cvec, and edge dtype flag -----------------------
__global__ __launch_bounds__(128) void prep_kernel(const float* __restrict__ W,
                                                   const float* __restrict__ bias,
                                                   const void* __restrict__ eidx) {
    int t = threadIdx.x;  // 0..127
    if (t == 0) {
        const ull* p = (const ull*)eidx;
        int is64 = 1;
        #pragma unroll
        for (int i = 0; i < 8; i++)
            if (p[i] >= (ull)NN) is64 = 0;
        g_is64 = is64;
    }
    for (int c = 0; c < CC; c++) {
        float v;
        if (t < 64) v = W[t * 192 + c] - W[t * 192 + 64 + c];   // W1 - W2
        else        v = W[(t - 64) * 192 + 64 + c];             // W2
        g_Mt[c][t] = v;
    }
    int b = t >> 6, o = t & 63;
    float s = bias[o];
    #pragma unroll 8
    for (int c = 0; c < CC; c++)
        s = fmaf(W[o * 192 + 128 + c], g_mean[b][c], s);        // W3 . mean
    g_cvec[b][o] = s;
}

// ---------------- GEMM: Yh[b][n][r] = sum_c Mt[c][r] * x[b][c][n] -----------
// grid (256, 2) = 512 blocks, 3 blocks/SM (48 KB smem), 24 warps/SM.
// Accumulator pairs over r: m-pairs load NATIVELY from smem (no packing);
// only 4 x-duplication MOVs per c. Per c-iter: 3 LDS.128 + 4 MOV + 16 FFMA2.
// Per-thread tile: 4 n x 8 r (acc = 16 ull = 32 regs).
__global__ __launch_bounds__(256, 3) void gemm_kernel(const float* __restrict__ x) {
    __shared__ __align__(16) float Ms[CC][RR];    // 32 KB
    __shared__ __align__(16) float Xs[CC][TNB];   // 16 KB
    int b   = blockIdx.y;
    int n0  = blockIdx.x * TNB;
    int tid = threadIdx.x;

    for (int i = tid; i < CC * RR / 4; i += 256)
        ((float4*)Ms)[i] = ((const float4*)g_Mt)[i];
    const float* xb = x + (size_t)b * CC * NN;
    for (int i = tid; i < CC * TNB / 4; i += 256) {
        int c = i >> 4, j = i & 15;   // TNB/4 = 16
        ((float4*)&Xs[c][0])[j] = ((const float4*)(xb + (size_t)c * NN + n0))[j];
    }
    __syncthreads();

    int rg = tid >> 4;    // 16 groups: r = rg*8 .. +7
    int ng = tid & 15;    // 16 groups: n = n0 + ng*4 .. +3
    // acc[a][q] = (out[r=rg*8+2q], out[r=rg*8+2q+1]) for node n0+ng*4+a
    ull acc[4][4];
    #pragma unroll
    for (int a = 0; a < 4; a++)
        #pragma unroll
        for (int q = 0; q < 4; q++) acc[a][q] = 0ull;

    #pragma unroll 4
    for (int c = 0; c < CC; c++) {
        // m: 8 consecutive r as 4 native (r,r+1) pairs — no packing needed
        ulonglong2 ma = *(const ulonglong2*)&Ms[c][rg * 8];      // pairs q=0,1
        ulonglong2 mb = *(const ulonglong2*)&Ms[c][rg * 8 + 4];  // pairs q=2,3
        float4 xv = *(const float4*)&Xs[c][ng * 4];
        ull xd[4];
        xd[0] = pack2(xv.x, xv.x);
        xd[1] = pack2(xv.y, xv.y);
        xd[2] = pack2(xv.z, xv.z);
        xd[3] = pack2(xv.w, xv.w);
        #pragma unroll
        for (int a = 0; a < 4; a++) {
            FMA_F32X2(acc[a][0], xd[a], ma.x);
            FMA_F32X2(acc[a][1], xd[a], ma.y);
            FMA_F32X2(acc[a][2], xd[a], mb.x);
            FMA_F32X2(acc[a][3], xd[a], mb.y);
        }
    }

    __half* Yb = g_Yh + (size_t)b * NN * RR;
    #pragma unroll
    for (int a = 0; a < 4; a++) {
        int n = n0 + ng * 4 + a;
        uint4 pk;
        unsigned* pku = (unsigned*)&pk;
        #pragma unroll
        for (int q = 0; q < 4; q++) {
            uint2 u = *(uint2*)&acc[a][q];   // (r even, r odd) floats
            __half2 h = __floats2half2_rn(__uint_as_float(u.x),
                                          __uint_as_float(u.y));
            pku[q] = *(unsigned*)&h;
        }
        *(uint4*)(Yb + (size_t)n * RR + rg * 8) = pk;
    }
}

// ---------------- gather + max-relu epilogue --------------------------------
// (frozen: measured-best configuration from round 12)
__global__ __launch_bounds__(256) void gather_kernel(const void* __restrict__ eidx,
                                                     float* __restrict__ out) {
    int bn   = blockIdx.x;               // 0..511
    int b    = bn >> 8;                  // 256 blocks per batch
    int n0   = (bn & 255) * 64;
    int tid  = threadIdx.x;
    int lane = tid & 31;
    int w    = tid >> 5;

    __shared__ int   s_idx[64][2][KK];   // 8 KB
    __shared__ float s_o[64][65];        // padded, conflict-free

    int is64 = g_is64;
    const long long* e64 = (const long long*)eidx;
    const int*       e32 = (const int*)eidx;
    for (int i = tid; i < 64 * KK; i += 256) {
        int ln = i >> 4, k = i & 15;
        size_t bj = ((size_t)(0 * BB + b) * NN + (n0 + ln)) * KK + k;
        size_t bi = ((size_t)(1 * BB + b) * NN + (n0 + ln)) * KK + k;
        int vi, vj;
        if (is64) { vj = (int)e64[bj]; vi = (int)e64[bi]; }
        else      { vj = e32[bj];      vi = e32[bi]; }
        s_idx[ln][0][k] = vi;            // center   (edge_index[1])
        s_idx[ln][1][k] = vj;            // neighbor (edge_index[0])
    }
    __syncthreads();

    float2 cv = ((const float2*)g_cvec[b])[lane];   // channels 2*lane, 2*lane+1
    const __half* Yb = g_Yh + (size_t)b * NN * RR;

    for (int t = 0; t < 8; t++) {
        int ln = w * 8 + t;
        float m0 = 0.f, m1 = 0.f;        // relu floor folded into max
        #pragma unroll
        for (int k = 0; k < KK; k++) {
            int i = s_idx[ln][0][k];
            int j = s_idx[ln][1][k];
            __half2 hi = ((const __half2*)(Yb + (size_t)i * RR))[lane];
            __half2 hj = ((const __half2*)(Yb + (size_t)j * RR + 64))[lane];
            float2 fi = __half22float2(hi);
            float2 fj = __half22float2(hj);
            m0 = fmaxf(m0, fi.x + fj.x + cv.x);
            m1 = fmaxf(m1, fi.y + fj.y + cv.y);
        }
        s_o[ln][2 * lane]     = m0;
        s_o[ln][2 * lane + 1] = m1;
    }
    __syncthreads();

    float* ob = out + (size_t)b * COUT * NN;
    for (int i = tid; i < COUT * 64; i += 256) {
        int ch = i >> 6, j = i & 63;
        ob[ch * NN + n0 + j] = s_o[j][ch];
    }
}

// ---------------- launch ----------------------------------------------------
extern "C" void kernel_launch(void* const* d_in, const int* in_sizes, int n_in,
                              void* d_out, int out_size) {
    const float* x    = (const float*)d_in[0];
    const void*  eidx = d_in[1];
    const float* W    = (const float*)d_in[2];
    const float* bias = (const float*)d_in[3];
    float* out = (float*)d_out;

    mean_kernel<<<BB * CC, 256>>>(x);
    prep_kernel<<<1, 128>>>(W, bias, eidx);
    gemm_kernel<<<dim3(NN / TNB, BB), 256>>>(x);
    gather_kernel<<<BB * NN / 64, 256>>>(eidx, out);
}

// round 16
// speedup vs baseline: 1.5783x; 1.5783x over previous
#include <cuda_runtime.h>
#include <cuda_fp16.h>

#define BB    2
#define CC    64
#define NN    16384
#define KK    16
#define COUT  64
#define RR    128           // rows of combined matrix [W1-W2 ; W2]
#define TNB   64            // GEMM nodes per block
#define GNB   32            // gather nodes per block

typedef unsigned long long ull;

// ---------------- scratch (device globals; no allocation allowed) ----------
__device__ float  g_mean[BB][CC];
__device__ float  g_cvec[BB][COUT];
__device__ float  g_Mt[CC][RR];                // transposed combined matrix [c][r]
__device__ __half g_Yh[(size_t)BB * NN * RR];  // 8 MB transformed features (fp16)
__device__ int    g_is64;

// ---------------- f32x2 helpers (sm_103a packed fp32 FMA) -------------------
#define FMA_F32X2(d, a, b) \
    asm("fma.rn.f32x2 %0, %1, %2, %0;" : "+l"(d) : "l"(a), "l"(b))

__device__ __forceinline__ ull pack2(float lo, float hi) {
    ull r;
    asm("mov.b64 %0, {%1, %2};" : "=l"(r) : "f"(lo), "f"(hi));
    return r;
}

// ---------------- mean over nodes: g_mean[b][c] -----------------------------
__global__ __launch_bounds__(256) void mean_kernel(const float* __restrict__ x) {
    int row = blockIdx.x;                 // b*CC + c
    const float4* xr = (const float4*)(x + (size_t)row * NN);
    int tid = threadIdx.x;

    float4 v[16];
    #pragma unroll
    for (int it = 0; it < 16; it++)
        v[it] = xr[tid + it * 256];

    float s0 = 0.f, s1 = 0.f, s2 = 0.f, s3 = 0.f;
    #pragma unroll
    for (int it = 0; it < 16; it += 4) {
        s0 += v[it    ].x + v[it    ].y + v[it    ].z + v[it    ].w;
        s1 += v[it + 1].x + v[it + 1].y + v[it + 1].z + v[it + 1].w;
        s2 += v[it + 2].x + v[it + 2].y + v[it + 2].z + v[it + 2].w;
        s3 += v[it + 3].x + v[it + 3].y + v[it + 3].z + v[it + 3].w;
    }
    float s = (s0 + s1) + (s2 + s3);

    #pragma unroll
    for (int off = 16; off > 0; off >>= 1)
        s += __shfl_xor_sync(0xFFFFFFFFu, s, off);

    __shared__ float sm[8];
    if ((tid & 31) == 0) sm[tid >> 5] = s;
    __syncthreads();
    if (tid == 0) {
        float t = 0.f;
        #pragma unroll
        for (int w = 0; w < 8; w++) t += sm[w];
        ((float*)g_mean)[row] = t * (1.0f / NN);
    }
}

// ---------------- build Mt, cvec, and edge dtype flag -----------------------
__global__ __launch_bounds__(128) void prep_kernel(const float* __restrict__ W,
                                                   const float* __restrict__ bias,
                                                   const void* __restrict__ eidx) {
    int t = threadIdx.x;  // 0..127
    if (t == 0) {
        const ull* p = (const ull*)eidx;
        int is64 = 1;
        #pragma unroll
        for (int i = 0; i < 8; i++)
            if (p[i] >= (ull)NN) is64 = 0;
        g_is64 = is64;
    }
    for (int c = 0; c < CC; c++) {
        float v;
        if (t < 64) v = W[t * 192 + c] - W[t * 192 + 64 + c];   // W1 - W2
        else        v = W[(t - 64) * 192 + 64 + c];             // W2
        g_Mt[c][t] = v;
    }
    int b = t >> 6, o = t & 63;
    float s = bias[o];
    #pragma unroll 8
    for (int c = 0; c < CC; c++)
        s = fmaf(W[o * 192 + 128 + c], g_mean[b][c], s);        // W3 . mean
    g_cvec[b][o] = s;
}

// ---------------- GEMM: Yh[b][n][r] = sum_c Mt[c][r] * x[b][c][n] -----------
// grid (256, 2) = 512 blocks, 3 blocks/SM (48 KB smem), 24 warps/SM.
// Accumulator pairs over r: m-pairs load NATIVELY from smem (no packing);
// only 4 x-duplication MOVs per c. Per-thread tile: 4 n x 8 r (acc 32 regs).
__global__ __launch_bounds__(256, 3) void gemm_kernel(const float* __restrict__ x) {
    __shared__ __align__(16) float Ms[CC][RR];    // 32 KB
    __shared__ __align__(16) float Xs[CC][TNB];   // 16 KB
    int b   = blockIdx.y;
    int n0  = blockIdx.x * TNB;
    int tid = threadIdx.x;

    for (int i = tid; i < CC * RR / 4; i += 256)
        ((float4*)Ms)[i] = ((const float4*)g_Mt)[i];
    const float* xb = x + (size_t)b * CC * NN;
    for (int i = tid; i < CC * TNB / 4; i += 256) {
        int c = i >> 4, j = i & 15;   // TNB/4 = 16
        ((float4*)&Xs[c][0])[j] = ((const float4*)(xb + (size_t)c * NN + n0))[j];
    }
    __syncthreads();

    int rg = tid >> 4;    // 16 groups: r = rg*8 .. +7
    int ng = tid & 15;    // 16 groups: n = n0 + ng*4 .. +3
    ull acc[4][4];
    #pragma unroll
    for (int a = 0; a < 4; a++)
        #pragma unroll
        for (int q = 0; q < 4; q++) acc[a][q] = 0ull;

    #pragma unroll 4
    for (int c = 0; c < CC; c++) {
        ulonglong2 ma = *(const ulonglong2*)&Ms[c][rg * 8];      // pairs q=0,1
        ulonglong2 mb = *(const ulonglong2*)&Ms[c][rg * 8 + 4];  // pairs q=2,3
        float4 xv = *(const float4*)&Xs[c][ng * 4];
        ull xd[4];
        xd[0] = pack2(xv.x, xv.x);
        xd[1] = pack2(xv.y, xv.y);
        xd[2] = pack2(xv.z, xv.z);
        xd[3] = pack2(xv.w, xv.w);
        #pragma unroll
        for (int a = 0; a < 4; a++) {
            FMA_F32X2(acc[a][0], xd[a], ma.x);
            FMA_F32X2(acc[a][1], xd[a], ma.y);
            FMA_F32X2(acc[a][2], xd[a], mb.x);
            FMA_F32X2(acc[a][3], xd[a], mb.y);
        }
    }

    __half* Yb = g_Yh + (size_t)b * NN * RR;
    #pragma unroll
    for (int a = 0; a < 4; a++) {
        int n = n0 + ng * 4 + a;
        uint4 pk;
        unsigned* pku = (unsigned*)&pk;
        #pragma unroll
        for (int q = 0; q < 4; q++) {
            uint2 u = *(uint2*)&acc[a][q];   // (r even, r odd) floats
            __half2 h = __floats2half2_rn(__uint_as_float(u.x),
                                          __uint_as_float(u.y));
            pku[q] = *(unsigned*)&h;
        }
        *(uint4*)(Yb + (size_t)n * RR + rg * 8) = pk;
    }
}

// ---------------- gather + max-relu epilogue --------------------------------
// 32 nodes/block -> grid 1024 (~7 blocks/SM): occupancy-driven latency hiding.
// Warp handles 4 nodes serially; per node 32 independent half2 row-loads.
// Indices pre-scaled to half offsets at staging (saves IMAD in hot loop).
__global__ __launch_bounds__(256) void gather_kernel(const void* __restrict__ eidx,
                                                     float* __restrict__ out) {
    int bn   = blockIdx.x;               // 0..1023
    int b    = bn >> 9;                  // 512 blocks per batch
    int n0   = (bn & 511) * GNB;
    int tid  = threadIdx.x;
    int lane = tid & 31;
    int w    = tid >> 5;

    __shared__ int   s_idx[GNB][2][KK];  // 4 KB (pre-scaled offsets)
    __shared__ float s_o[GNB][65];       // 8.3 KB, padded

    int is64 = g_is64;
    const long long* e64 = (const long long*)eidx;
    const int*       e32 = (const int*)eidx;
    for (int i = tid; i < GNB * KK; i += 256) {
        int ln = i >> 4, k = i & 15;
        size_t bj = ((size_t)(0 * BB + b) * NN + (n0 + ln)) * KK + k;
        size_t bi = ((size_t)(1 * BB + b) * NN + (n0 + ln)) * KK + k;
        int vi, vj;
        if (is64) { vj = (int)e64[bj]; vi = (int)e64[bi]; }
        else      { vj = e32[bj];      vi = e32[bi]; }
        s_idx[ln][0][k] = vi * RR;           // center   (edge_index[1]) -> Y row
        s_idx[ln][1][k] = vj * RR + 64;      // neighbor (edge_index[0]) -> Y row+64
    }
    __syncthreads();

    float2 cv = ((const float2*)g_cvec[b])[lane];   // channels 2*lane, 2*lane+1
    const __half* Yb = g_Yh + (size_t)b * NN * RR;

    #pragma unroll
    for (int t = 0; t < 4; t++) {
        int ln = w * 4 + t;
        float m0 = 0.f, m1 = 0.f;        // relu floor folded into max
        #pragma unroll
        for (int k = 0; k < KK; k++) {
            int oi = s_idx[ln][0][k];
            int oj = s_idx[ln][1][k];
            __half2 hi = ((const __half2*)(Yb + oi))[lane];
            __half2 hj = ((const __half2*)(Yb + oj))[lane];
            float2 fi = __half22float2(hi);
            float2 fj = __half22float2(hj);
            m0 = fmaxf(m0, fi.x + fj.x + cv.x);
            m1 = fmaxf(m1, fi.y + fj.y + cv.y);
        }
        s_o[ln][2 * lane]     = m0;
        s_o[ln][2 * lane + 1] = m1;
    }
    __syncthreads();

    float* ob = out + (size_t)b * COUT * NN;
    for (int i = tid; i < COUT * GNB; i += 256) {
        int ch = i >> 5, j = i & 31;
        ob[ch * NN + n0 + j] = s_o[j][ch];
    }
}

// ---------------- launch ----------------------------------------------------
extern "C" void kernel_launch(void* const* d_in, const int* in_sizes, int n_in,
                              void* d_out, int out_size) {
    const float* x    = (const float*)d_in[0];
    const void*  eidx = d_in[1];
    const float* W    = (const float*)d_in[2];
    const float* bias = (const float*)d_in[3];
    float* out = (float*)d_out;

    mean_kernel<<<BB * CC, 256>>>(x);
    prep_kernel<<<1, 128>>>(W, bias, eidx);
    gemm_kernel<<<dim3(NN / TNB, BB), 256>>>(x);
    gather_kernel<<<BB * NN / GNB, 256>>>(eidx, out);
}

// round 17
// speedup vs baseline: 1.5875x; 1.0058x over previous
#include <cuda_runtime.h>
#include <cuda_fp16.h>

#define BB    2
#define CC    64
#define NN    16384
#define KK    16
#define COUT  64
#define RR    128           // rows of combined matrix [W1-W2 ; W2]
#define GNB   32            // gather nodes per block
#define TN    128           // gemm n-tile per block

typedef unsigned long long ull;
typedef unsigned int uint;

// ---------------- scratch (device globals; no allocation allowed) ----------
__device__ float  g_mean[BB][CC];
__device__ float  g_cvec[BB][COUT];
__device__ __half g_Mh[RR * CC];               // combined matrix fp16, row-major [r][c]
__device__ __half g_Yh[(size_t)BB * NN * RR];  // 8 MB transformed features (fp16)
__device__ int    g_is64;

// ---------------- mma helpers ------------------------------------------------
__device__ __forceinline__ uint sptr(const void* p) {
    return (uint)__cvta_generic_to_shared(p);
}

__device__ __forceinline__ void ldsm_x4(uint& r0, uint& r1, uint& r2, uint& r3,
                                        uint addr) {
    asm volatile("ldmatrix.sync.aligned.m8n8.x4.shared.b16 {%0,%1,%2,%3}, [%4];"
                 : "=r"(r0), "=r"(r1), "=r"(r2), "=r"(r3) : "r"(addr));
}

__device__ __forceinline__ void ldsm_x4_t(uint& r0, uint& r1, uint& r2, uint& r3,
                                          uint addr) {
    asm volatile("ldmatrix.sync.aligned.m8n8.x4.trans.shared.b16 {%0,%1,%2,%3}, [%4];"
                 : "=r"(r0), "=r"(r1), "=r"(r2), "=r"(r3) : "r"(addr));
}

__device__ __forceinline__ void mma_16816(float* d, const uint* a, uint b0, uint b1) {
    asm volatile(
        "mma.sync.aligned.m16n8k16.row.col.f32.f16.f16.f32 "
        "{%0,%1,%2,%3}, {%4,%5,%6,%7}, {%8,%9}, {%0,%1,%2,%3};"
        : "+f"(d[0]), "+f"(d[1]), "+f"(d[2]), "+f"(d[3])
        : "r"(a[0]), "r"(a[1]), "r"(a[2]), "r"(a[3]), "r"(b0), "r"(b1));
}

// ---------------- mean over nodes: g_mean[b][c] -----------------------------
__global__ __launch_bounds__(256) void mean_kernel(const float* __restrict__ x) {
    int row = blockIdx.x;                 // b*CC + c
    const float4* xr = (const float4*)(x + (size_t)row * NN);
    int tid = threadIdx.x;

    float4 v[16];
    #pragma unroll
    for (int it = 0; it < 16; it++)
        v[it] = xr[tid + it * 256];

    float s0 = 0.f, s1 = 0.f, s2 = 0.f, s3 = 0.f;
    #pragma unroll
    for (int it = 0; it < 16; it += 4) {
        s0 += v[it    ].x + v[it    ].y + v[it    ].z + v[it    ].w;
        s1 += v[it + 1].x + v[it + 1].y + v[it + 1].z + v[it + 1].w;
        s2 += v[it + 2].x + v[it + 2].y + v[it + 2].z + v[it + 2].w;
        s3 += v[it + 3].x + v[it + 3].y + v[it + 3].z + v[it + 3].w;
    }
    float s = (s0 + s1) + (s2 + s3);

    #pragma unroll
    for (int off = 16; off > 0; off >>= 1)
        s += __shfl_xor_sync(0xFFFFFFFFu, s, off);

    __shared__ float sm[8];
    if ((tid & 31) == 0) sm[tid >> 5] = s;
    __syncthreads();
    if (tid == 0) {
        float t = 0.f;
        #pragma unroll
        for (int w = 0; w < 8; w++) t += sm[w];
        ((float*)g_mean)[row] = t * (1.0f / NN);
    }
}

// ---------------- build Mh (fp16 [r][c]), cvec, edge dtype flag --------------
__global__ __launch_bounds__(128) void prep_kernel(const float* __restrict__ W,
                                                   const float* __restrict__ bias,
                                                   const void* __restrict__ eidx) {
    int t = threadIdx.x;  // 0..127 = output row r
    if (t == 0) {
        const ull* p = (const ull*)eidx;
        int is64 = 1;
        #pragma unroll
        for (int i = 0; i < 8; i++)
            if (p[i] >= (ull)NN) is64 = 0;
        g_is64 = is64;
    }
    for (int c = 0; c < CC; c++) {
        float v;
        if (t < 64) v = W[t * 192 + c] - W[t * 192 + 64 + c];   // W1 - W2
        else        v = W[(t - 64) * 192 + 64 + c];             // W2
        g_Mh[t * CC + c] = __float2half(v);
    }
    int b = t >> 6, o = t & 63;
    float s = bias[o];
    #pragma unroll 8
    for (int c = 0; c < CC; c++)
        s = fmaf(W[o * 192 + 128 + c], g_mean[b][c], s);        // W3 . mean
    g_cvec[b][o] = s;
}

// ---------------- GEMM (tensor cores): Yh[b][n][r] = M[r][:] . x[b][:][n] ----
// Block: 256 thr = 8 warps; tile 128 r x 128 n, full K=64.
// Warp w computes r-strip [w*16, w*16+16) x all 128 n.
// A = Ms[r][c] fp16 (ldmatrix.x4), B = Xs[c][n] fp16 (ldmatrix.x4.trans).
// Row strides 72/136 halfs keep ldmatrix rows 16B-aligned & conflict-free.
#define MS_STRIDE 72
#define XS_STRIDE 136
#define MS_BYTES  (RR * MS_STRIDE * 2)          // 18432
#define XS_BYTES  (CC * XS_STRIDE * 2)          // 17408
#define YS_STRIDE 136                           // staging [n][r], pad

__global__ __launch_bounds__(256) void gemm_kernel(const float* __restrict__ x) {
    __shared__ __align__(16) char smem[MS_BYTES + XS_BYTES];   // 35840 B
    __half* Ms = (__half*)smem;                    // [r][MS_STRIDE]
    __half* Xs = (__half*)(smem + MS_BYTES);       // [c][XS_STRIDE]
    __half* Ys = (__half*)smem;                    // reuse: [n][YS_STRIDE]

    int b   = blockIdx.y;
    int n0  = blockIdx.x * TN;
    int tid = threadIdx.x;
    int lane = tid & 31;
    int w    = tid >> 5;

    // stage M: 128x64 halfs = 1024 uint4
    for (int i = tid; i < 1024; i += 256) {
        int r = i >> 3, cq = i & 7;
        *(uint4*)(Ms + r * MS_STRIDE + cq * 8) =
            *(const uint4*)(g_Mh + r * CC + cq * 8);
    }
    // stage x tile: convert fp32 -> fp16;  Xs[c][j] = x[b][c][n0+j]
    const float* xb = x + (size_t)b * CC * NN;
    for (int i = tid; i < CC * (TN / 4); i += 256) {
        int c = i >> 5, j = i & 31;                 // j: group of 4 n
        float4 v = *(const float4*)(xb + (size_t)c * NN + n0 + j * 4);
        __half2 h0 = __floats2half2_rn(v.x, v.y);
        __half2 h1 = __floats2half2_rn(v.z, v.w);
        uint2 pk;
        pk.x = *(uint*)&h0; pk.y = *(uint*)&h1;
        *(uint2*)(Xs + c * XS_STRIDE + j * 4) = pk;
    }
    __syncthreads();

    float acc[16][4];
    #pragma unroll
    for (int ni = 0; ni < 16; ni++)
        #pragma unroll
        for (int q = 0; q < 4; q++) acc[ni][q] = 0.f;

    // ldmatrix lane addressing: row = base_row + (lane&15), col = base_col + (lane>>4)*8
    int lrow = lane & 15;
    int lcol = (lane >> 4) * 8;

    #pragma unroll
    for (int kk = 0; kk < 4; kk++) {                // c0 = kk*16
        int c0 = kk * 16;
        uint a[4];
        {
            uint addr = sptr(Ms + (w * 16 + lrow) * MS_STRIDE + c0 + lcol);
            ldsm_x4(a[0], a[1], a[2], a[3], addr);
        }
        #pragma unroll
        for (int nb = 0; nb < 8; nb++) {            // n = nb*16 .. +15
            uint b0, b1, b2, b3;
            uint addr = sptr(Xs + (c0 + lrow) * XS_STRIDE + nb * 16 + lcol);
            ldsm_x4_t(b0, b1, b2, b3, addr);
            mma_16816(acc[2 * nb],     a, b0, b1);  // n-tile nb*16
            mma_16816(acc[2 * nb + 1], a, b2, b3);  // n-tile nb*16+8
        }
    }
    __syncthreads();

    // stage D -> Ys[n][r] fp16 (scalar stores; one-time)
    {
        int rl = w * 16 + (lane >> 2);              // rows rl, rl+8
        int nl = 2 * (lane & 3);                    // cols nl, nl+1 within n-tile
        #pragma unroll
        for (int ni = 0; ni < 16; ni++) {
            int n = ni * 8 + nl;
            Ys[n * YS_STRIDE + rl]           = __float2half(acc[ni][0]);
            Ys[(n + 1) * YS_STRIDE + rl]     = __float2half(acc[ni][1]);
            Ys[n * YS_STRIDE + rl + 8]       = __float2half(acc[ni][2]);
            Ys[(n + 1) * YS_STRIDE + rl + 8] = __float2half(acc[ni][3]);
        }
    }
    __syncthreads();

    // coalesced write: g_Yh[b][n0+n][r], 128 n x 16 uint4
    __half* Yb = g_Yh + (size_t)b * NN * RR;
    for (int i = tid; i < TN * 16; i += 256) {
        int n = i >> 4, rq = i & 15;
        *(uint4*)(Yb + (size_t)(n0 + n) * RR + rq * 8) =
            *(const uint4*)(Ys + n * YS_STRIDE + rq * 8);
    }
}

// ---------------- gather + max-relu epilogue --------------------------------
// (frozen: measured-best configuration from round 16)
__global__ __launch_bounds__(256) void gather_kernel(const void* __restrict__ eidx,
                                                     float* __restrict__ out) {
    int bn   = blockIdx.x;               // 0..1023
    int b    = bn >> 9;                  // 512 blocks per batch
    int n0   = (bn & 511) * GNB;
    int tid  = threadIdx.x;
    int lane = tid & 31;
    int w    = tid >> 5;

    __shared__ int   s_idx[GNB][2][KK];  // 4 KB (pre-scaled offsets)
    __shared__ float s_o[GNB][65];       // 8.3 KB, padded

    int is64 = g_is64;
    const long long* e64 = (const long long*)eidx;
    const int*       e32 = (const int*)eidx;
    for (int i = tid; i < GNB * KK; i += 256) {
        int ln = i >> 4, k = i & 15;
        size_t bj = ((size_t)(0 * BB + b) * NN + (n0 + ln)) * KK + k;
        size_t bi = ((size_t)(1 * BB + b) * NN + (n0 + ln)) * KK + k;
        int vi, vj;
        if (is64) { vj = (int)e64[bj]; vi = (int)e64[bi]; }
        else      { vj = e32[bj];      vi = e32[bi]; }
        s_idx[ln][0][k] = vi * RR;           // center   (edge_index[1]) -> Y row
        s_idx[ln][1][k] = vj * RR + 64;      // neighbor (edge_index[0]) -> Y row+64
    }
    __syncthreads();

    float2 cv = ((const float2*)g_cvec[b])[lane];   // channels 2*lane, 2*lane+1
    const __half* Yb = g_Yh + (size_t)b * NN * RR;

    #pragma unroll
    for (int t = 0; t < 4; t++) {
        int ln = w * 4 + t;
        float m0 = 0.f, m1 = 0.f;        // relu floor folded into max
        #pragma unroll
        for (int k = 0; k < KK; k++) {
            int oi = s_idx[ln][0][k];
            int oj = s_idx[ln][1][k];
            __half2 hi = ((const __half2*)(Yb + oi))[lane];
            __half2 hj = ((const __half2*)(Yb + oj))[lane];
            float2 fi = __half22float2(hi);
            float2 fj = __half22float2(hj);
            m0 = fmaxf(m0, fi.x + fj.x + cv.x);
            m1 = fmaxf(m1, fi.y + fj.y + cv.y);
        }
        s_o[ln][2 * lane]     = m0;
        s_o[ln][2 * lane + 1] = m1;
    }
    __syncthreads();

    float* ob = out + (size_t)b * COUT * NN;
    for (int i = tid; i < COUT * GNB; i += 256) {
        int ch = i >> 5, j = i & 31;
        ob[ch * NN + n0 + j] = s_o[j][ch];
    }
}

// ---------------- launch ----------------------------------------------------
extern "C" void kernel_launch(void* const* d_in, const int* in_sizes, int n_in,
                              void* d_out, int out_size) {
    const float* x    = (const float*)d_in[0];
    const void*  eidx = d_in[1];
    const float* W    = (const float*)d_in[2];
    const float* bias = (const float*)d_in[3];
    float* out = (float*)d_out;

    mean_kernel<<<BB * CC, 256>>>(x);
    prep_kernel<<<1, 128>>>(W, bias, eidx);
    gemm_kernel<<<dim3(NN / TN, BB), 256>>>(x);
    gather_kernel<<<BB * NN / GNB, 256>>>(eidx, out);
}